// round 5
// baseline (speedup 1.0000x reference)
#include <cuda_runtime.h>

// Problem constants
#define B_  8192
#define T_  336
#define F_  8
#define H_  20
#define G_  80           // 4*H gate rows
#define NPAIR (B_ / 2)   // 4096

typedef unsigned long long u64;

// Inter-layer hidden sequences, pair-interleaved: g_buf[pair][t][unit] = {h_e0, h_e1}
__device__ u64 g_buf0[(size_t)NPAIR * T_ * H_];
__device__ u64 g_buf1[(size_t)NPAIR * T_ * H_];

// ---- packed f32x2 helpers (sm_103a) ----
__device__ __forceinline__ u64 pk(float lo, float hi) {
    u64 r; asm("mov.b64 %0, {%1, %2};" : "=l"(r) : "f"(lo), "f"(hi)); return r;
}
__device__ __forceinline__ float2 upk(u64 v) {
    float2 f; asm("mov.b64 {%0, %1}, %2;" : "=f"(f.x), "=f"(f.y) : "l"(v)); return f;
}
__device__ __forceinline__ u64 ffma2(u64 a, u64 b, u64 c) {
    u64 d; asm("fma.rn.f32x2 %0, %1, %2, %3;" : "=l"(d) : "l"(a), "l"(b), "l"(c)); return d;
}
__device__ __forceinline__ u64 fmul2(u64 a, u64 b) {
    u64 d; asm("mul.rn.f32x2 %0, %1, %2;" : "=l"(d) : "l"(a), "l"(b)); return d;
}
__device__ __forceinline__ u64 fadd2(u64 a, u64 b) {
    u64 d; asm("add.rn.f32x2 %0, %1, %2;" : "=l"(d) : "l"(a), "l"(b)); return d;
}
__device__ __forceinline__ float sig1(float x) {
    return __fdividef(1.f, 1.f + __expf(-x));
}

// ============================================================================
// Layer 0 kernel: IN=8, one thread per gate row (known-good R3 design)
// ============================================================================
#define PPB0 4
__global__ __launch_bounds__(PPB0 * G_)
void lstm_l0(
    const float* __restrict__ in_seq,
    const float* __restrict__ W_ih,   // [80, 8]
    const float* __restrict__ W_hh,   // [80, 20]
    const float* __restrict__ b_ih,
    const float* __restrict__ b_hh)
{
    constexpr int IN = F_;
    constexpr int KTOT = IN + H_;        // 28
    constexpr int K2   = KTOT / 2;       // 14

    __shared__ ulonglong2 s_hx[2][PPB0][K2];
    __shared__ u64 s_g[PPB0][G_];

    const int tid  = threadIdx.x;
    const int e    = tid / G_;
    const int g    = tid % G_;
    const int unit = g % H_;
    const int type = g / H_;
    const size_t pair = (size_t)blockIdx.x * PPB0 + e;

    u64 w2[KTOT];
    #pragma unroll
    for (int k = 0; k < IN; ++k) { float w = __ldg(&W_ih[g * IN + k]); w2[k] = pk(w, w); }
    #pragma unroll
    for (int k = 0; k < H_; ++k) { float w = __ldg(&W_hh[g * H_ + k]); w2[IN + k] = pk(w, w); }
    const float bb = __ldg(&b_ih[g]) + __ldg(&b_hh[g]);
    const u64 bias2 = pk(bb, bb);
    const float sc = (type == 2) ? -2.f : -1.f;
    const float am = (type == 2) ?  2.f :  1.f;
    const float bm = (type == 2) ? -1.f :  0.f;

    const float* __restrict__ inp_f0 = in_seq + (size_t)(2 * pair)     * T_ * IN;
    const float* __restrict__ inp_f1 = in_seq + (size_t)(2 * pair + 1) * T_ * IN;
    u64* __restrict__ outp = g_buf0 + pair * T_ * H_;

    float xr_f = 0.f;
    const int kx = g >> 1, elx = g & 1;

    {
        float* f0 = (float*)&s_hx[0][e][0];
        if (g < 2 * IN) {
            const float* ip = elx ? inp_f1 : inp_f0;
            f0[2 * kx + elx] = ip[kx];
            xr_f = ip[IN + kx];
        }
        if (g >= 20 && g < 20 + H_)
            ((u64*)f0)[IN + (g - 20)] = 0ULL;
    }
    __syncthreads();

    u64 c2 = 0ULL;
    int cur = 0;

    for (int t = 0; t < T_; ++t) {
        float* fn = (float*)&s_hx[cur ^ 1][e][0];
        if (g < 2 * IN) {
            if (t + 1 < T_) fn[2 * kx + elx] = xr_f;
            if (t + 2 < T_) {
                const float* ip = elx ? inp_f1 : inp_f0;
                xr_f = ip[(size_t)(t + 2) * IN + kx];
            }
        }

        const ulonglong2* hx = &s_hx[cur][e][0];
        u64 acc0 = bias2, acc1 = pk(0.f, 0.f);
        #pragma unroll
        for (int q = 0; q < K2; ++q) {
            ulonglong2 v = hx[q];
            acc0 = ffma2(v.x, w2[2 * q],     acc0);
            acc1 = ffma2(v.y, w2[2 * q + 1], acc1);
        }
        float2 a = upk(fadd2(acc0, acc1));

        float y0 = __fdividef(1.f, 1.f + __expf(sc * a.x));
        float y1 = __fdividef(1.f, 1.f + __expf(sc * a.y));
        s_g[e][g] = pk(fmaf(am, y0, bm), fmaf(am, y1, bm));

        __syncthreads();

        if (type == 0) {
            u64 ig = s_g[e][unit];
            u64 fg = s_g[e][unit + 20];
            u64 gg = s_g[e][unit + 40];
            u64 og = s_g[e][unit + 60];
            c2 = ffma2(fg, c2, fmul2(ig, gg));
            float2 cf = upk(c2);
            float t0 = fmaf(2.f, sig1(2.f * cf.x), -1.f);
            float t1 = fmaf(2.f, sig1(2.f * cf.y), -1.f);
            u64 h2 = fmul2(og, pk(t0, t1));
            ((u64*)fn)[IN + unit] = h2;
            outp[(size_t)t * H_ + unit] = h2;
        }

        __syncthreads();
        cur ^= 1;
    }
}

// ============================================================================
// Layers 1/2: K-split kernel. 160 threads per pair (gate g x K-half kh),
// 2 pairs per block, 2 blocks/SM. kh0 = x-part (W_ih), kh1 = h-part (W_hh).
// DST: 1 = g_buf0 -> g_buf1 ; 2 = g_buf1 -> FC head -> out
// ============================================================================
#define PPBK 2
template <int DST>
__global__ __launch_bounds__(320, 2)
void lstm_ksplit(
    const float* __restrict__ W_ih,   // [80, 20]
    const float* __restrict__ W_hh,   // [80, 20]
    const float* __restrict__ b_ih,
    const float* __restrict__ b_hh,
    const float* __restrict__ fc1_w,
    const float* __restrict__ fc1_b,
    const float* __restrict__ fc2_w,
    const float* __restrict__ fc2_b,
    float* __restrict__ out_final)
{
    constexpr bool FINAL = (DST == 2);
    constexpr int KH = 20;               // k-slots per half (u64 each)

    // [buf][pair][section(kh)][10 x 16B]
    __shared__ ulonglong2 s_hx[2][PPBK][2][KH / 2];
    __shared__ u64 s_g[PPBK][G_];

    const int tid  = threadIdx.x;
    const int e    = tid / 160;          // warp-pure: warps 0-4 e0, 5-9 e1
    const int r    = tid % 160;
    const int g    = r >> 1;             // gate row 0..79
    const int kh   = r & 1;              // K-half
    const int unit = g % H_;
    const int type = g / H_;
    const size_t pair = (size_t)blockIdx.x * PPBK + e;

    // weights for this K-half only: 20 u64 = 40 regs
    u64 w2[KH];
    #pragma unroll
    for (int k = 0; k < KH; ++k) {
        float w = kh ? __ldg(&W_hh[g * H_ + k]) : __ldg(&W_ih[g * H_ + k]);
        w2[k] = pk(w, w);
    }
    float bb = kh ? 0.f : (__ldg(&b_ih[g]) + __ldg(&b_hh[g]));
    const u64 bias2 = pk(bb, bb);
    const float sc = (type == 2) ? -2.f : -1.f;
    const float am = (type == 2) ?  2.f :  1.f;
    const float bm = (type == 2) ? -1.f :  0.f;

    const u64* __restrict__ inp_u = ((DST == 1) ? g_buf0 : g_buf1) + pair * T_ * H_;
    u64* __restrict__ outp = FINAL ? nullptr : g_buf1 + pair * T_ * H_;

    const bool is_owner = (type == 0) && (kh == 0);   // r = 2*unit
    const bool is_stage = (type == 0) && (kh == 1);   // r = 2*g+1, g<20

    // prologue: x0 -> buf0 sec0, h=0 -> buf0 sec1, prefetch x1
    u64 xr = 0;
    if (is_stage) {
        ((u64*)&s_hx[0][e][0][0])[g] = inp_u[g];
        xr = inp_u[H_ + g];
    }
    if (is_owner) ((u64*)&s_hx[0][e][1][0])[unit] = 0ULL;
    __syncthreads();

    u64 c2 = 0ULL;
    int cur = 0;

    for (int t = 0; t < T_; ++t) {
        // stage x[t+1] into next buffer sec0; prefetch x[t+2]
        if (is_stage) {
            if (t + 1 < T_) ((u64*)&s_hx[cur ^ 1][e][0][0])[g] = xr;
            if (t + 2 < T_) xr = inp_u[(size_t)(t + 2) * H_ + g];
        }

        // half-gate dot: 10 LDS.128 + 20 FFMA2
        const ulonglong2* sec = &s_hx[cur][e][kh][0];
        u64 acc0 = bias2, acc1 = pk(0.f, 0.f);
        #pragma unroll
        for (int q = 0; q < KH / 2; ++q) {
            ulonglong2 v = sec[q];
            acc0 = ffma2(v.x, w2[2 * q],     acc0);
            acc1 = ffma2(v.y, w2[2 * q + 1], acc1);
        }
        float2 af = upk(fadd2(acc0, acc1));

        // combine with K-half partner (lane^1, same warp)
        af.x += __shfl_xor_sync(0xFFFFFFFFu, af.x, 1);
        af.y += __shfl_xor_sync(0xFFFFFFFFu, af.y, 1);

        // activation (redundant across the lane pair - free)
        float y0 = __fdividef(1.f, 1.f + __expf(sc * af.x));
        float y1 = __fdividef(1.f, 1.f + __expf(sc * af.y));
        if (kh == 0) s_g[e][g] = pk(fmaf(am, y0, bm), fmaf(am, y1, bm));

        __syncthreads();

        if (is_owner) {
            u64 ig = s_g[e][unit];
            u64 fg = s_g[e][unit + 20];
            u64 gg = s_g[e][unit + 40];
            u64 og = s_g[e][unit + 60];
            c2 = ffma2(fg, c2, fmul2(ig, gg));
            float2 cf = upk(c2);
            float t0 = fmaf(2.f, sig1(2.f * cf.x), -1.f);
            float t1 = fmaf(2.f, sig1(2.f * cf.y), -1.f);
            u64 h2 = fmul2(og, pk(t0, t1));
            ((u64*)&s_hx[cur ^ 1][e][1][0])[unit] = h2;
            if (!FINAL) outp[(size_t)t * H_ + unit] = h2;
        }

        __syncthreads();
        cur ^= 1;
    }

    if (FINAL) {
        const u64* hfin = (const u64*)&s_hx[cur][e][1][0];
        if (is_owner) {
            float b1 = __ldg(&fc1_b[unit]);
            u64 d2 = pk(b1, b1);
            #pragma unroll
            for (int k = 0; k < H_; ++k) {
                float w = __ldg(&fc1_w[unit * H_ + k]);
                d2 = ffma2(hfin[k], pk(w, w), d2);
            }
            float2 df = upk(d2);
            float wo = __ldg(&fc2_w[unit]);
            s_g[e][unit] = pk(fmaxf(df.x, 0.f) * wo, fmaxf(df.y, 0.f) * wo);
        }
        __syncthreads();
        if (r == 0) {
            float p0 = __ldg(&fc2_b[0]), p1 = p0;
            #pragma unroll
            for (int k = 0; k < H_; ++k) {
                float2 v = upk(s_g[e][k]);
                p0 += v.x; p1 += v.y;
            }
            *(float2*)&out_final[2 * pair] = make_float2(p0, p1);
        }
    }
}

extern "C" void kernel_launch(void* const* d_in, const int* in_sizes, int n_in,
                              void* d_out, int out_size) {
    const float* x     = (const float*)d_in[0];
    const float* Wih0  = (const float*)d_in[1];
    const float* Whh0  = (const float*)d_in[2];
    const float* bih0  = (const float*)d_in[3];
    const float* bhh0  = (const float*)d_in[4];
    const float* Wih1  = (const float*)d_in[5];
    const float* Whh1  = (const float*)d_in[6];
    const float* bih1  = (const float*)d_in[7];
    const float* bhh1  = (const float*)d_in[8];
    const float* Wih2  = (const float*)d_in[9];
    const float* Whh2  = (const float*)d_in[10];
    const float* bih2  = (const float*)d_in[11];
    const float* bhh2  = (const float*)d_in[12];
    const float* fc1w  = (const float*)d_in[13];
    const float* fc1b  = (const float*)d_in[14];
    const float* fc2w  = (const float*)d_in[15];
    const float* fc2b  = (const float*)d_in[16];
    float* out = (float*)d_out;

    // Layer 0: x -> g_buf0
    lstm_l0<<<NPAIR / PPB0, PPB0 * G_>>>(x, Wih0, Whh0, bih0, bhh0);
    // Layer 1: g_buf0 -> g_buf1
    lstm_ksplit<1><<<NPAIR / PPBK, 320>>>(
        Wih1, Whh1, bih1, bhh1, nullptr, nullptr, nullptr, nullptr, nullptr);
    // Layer 2 + FC head: g_buf1 -> out
    lstm_ksplit<2><<<NPAIR / PPBK, 320>>>(
        Wih2, Whh2, bih2, bhh2, fc1w, fc1b, fc2w, fc2b, out);
}

// round 7
// speedup vs baseline: 1.4526x; 1.4526x over previous
#include <cuda_runtime.h>

// Problem constants
#define B_  8192
#define T_  336
#define F_  8
#define H_  20
#define G_  80
#define NPAIR (B_ / 2)   // 4096

typedef unsigned long long u64;

// Inter-layer hidden sequences, pair-interleaved: g_buf[pair][t][unit] = {h_e0, h_e1}
__device__ u64 g_buf0[(size_t)NPAIR * T_ * H_];
__device__ u64 g_buf1[(size_t)NPAIR * T_ * H_];

// ---- packed f32x2 helpers (sm_103a) ----
__device__ __forceinline__ u64 pk(float lo, float hi) {
    u64 r; asm("mov.b64 %0, {%1, %2};" : "=l"(r) : "f"(lo), "f"(hi)); return r;
}
__device__ __forceinline__ float2 upk(u64 v) {
    float2 f; asm("mov.b64 {%0, %1}, %2;" : "=f"(f.x), "=f"(f.y) : "l"(v)); return f;
}
__device__ __forceinline__ u64 ffma2(u64 a, u64 b, u64 c) {
    u64 d; asm("fma.rn.f32x2 %0, %1, %2, %3;" : "=l"(d) : "l"(a), "l"(b), "l"(c)); return d;
}
__device__ __forceinline__ u64 fmul2(u64 a, u64 b) {
    u64 d; asm("mul.rn.f32x2 %0, %1, %2;" : "=l"(d) : "l"(a), "l"(b)); return d;
}
__device__ __forceinline__ u64 fadd2(u64 a, u64 b) {
    u64 d; asm("add.rn.f32x2 %0, %1, %2;" : "=l"(d) : "l"(a), "l"(b)); return d;
}
__device__ __forceinline__ float sig1(float x) {
    return __fdividef(1.f, 1.f + __expf(-x));
}

// ============================================================================
// Layer 0: EXACT R4 kernel (proven). IN=8, 4 pairs/block, 320 threads.
// x (float gmem) -> g_buf0 (pair-packed u64)
// ============================================================================
#define PPB0 4
__global__ __launch_bounds__(PPB0 * G_)
void lstm_l0(
    const float* __restrict__ in_seq,
    const float* __restrict__ W_ih,   // [80, 8]
    const float* __restrict__ W_hh,   // [80, 20]
    const float* __restrict__ b_ih,
    const float* __restrict__ b_hh)
{
    constexpr int IN = F_;
    constexpr int KTOT = IN + H_;        // 28
    constexpr int K2   = KTOT / 2;       // 14

    __shared__ ulonglong2 s_hx[2][PPB0][K2];
    __shared__ u64 s_g[PPB0][G_];

    const int tid  = threadIdx.x;
    const int e    = tid / G_;
    const int g    = tid % G_;
    const int unit = g % H_;
    const int type = g / H_;
    const size_t pair = (size_t)blockIdx.x * PPB0 + e;

    u64 w2[KTOT];
    #pragma unroll
    for (int k = 0; k < IN; ++k) { float w = __ldg(&W_ih[g * IN + k]); w2[k] = pk(w, w); }
    #pragma unroll
    for (int k = 0; k < H_; ++k) { float w = __ldg(&W_hh[g * H_ + k]); w2[IN + k] = pk(w, w); }
    const float bb = __ldg(&b_ih[g]) + __ldg(&b_hh[g]);
    const u64 bias2 = pk(bb, bb);
    const float sc = (type == 2) ? -2.f : -1.f;
    const float am = (type == 2) ?  2.f :  1.f;
    const float bm = (type == 2) ? -1.f :  0.f;

    const float* __restrict__ inp_f0 = in_seq + (size_t)(2 * pair)     * T_ * IN;
    const float* __restrict__ inp_f1 = in_seq + (size_t)(2 * pair + 1) * T_ * IN;
    u64* __restrict__ outp = g_buf0 + pair * T_ * H_;

    float xr_f = 0.f;
    const int kx = g >> 1, elx = g & 1;

    {
        float* f0 = (float*)&s_hx[0][e][0];
        if (g < 2 * IN) {
            const float* ip = elx ? inp_f1 : inp_f0;
            f0[2 * kx + elx] = ip[kx];
            xr_f = ip[IN + kx];
        }
        if (g >= 20 && g < 20 + H_)
            ((u64*)f0)[IN + (g - 20)] = 0ULL;
    }
    __syncthreads();

    u64 c2 = 0ULL;
    int cur = 0;

    for (int t = 0; t < T_; ++t) {
        float* fn = (float*)&s_hx[cur ^ 1][e][0];
        if (g < 2 * IN) {
            if (t + 1 < T_) fn[2 * kx + elx] = xr_f;
            if (t + 2 < T_) {
                const float* ip = elx ? inp_f1 : inp_f0;
                xr_f = ip[(size_t)(t + 2) * IN + kx];
            }
        }

        const ulonglong2* hx = &s_hx[cur][e][0];
        u64 acc0 = bias2, acc1 = pk(0.f, 0.f);
        #pragma unroll
        for (int q = 0; q < K2; ++q) {
            ulonglong2 v = hx[q];
            acc0 = ffma2(v.x, w2[2 * q],     acc0);
            acc1 = ffma2(v.y, w2[2 * q + 1], acc1);
        }
        float2 a = upk(fadd2(acc0, acc1));

        float y0 = __fdividef(1.f, 1.f + __expf(sc * a.x));
        float y1 = __fdividef(1.f, 1.f + __expf(sc * a.y));
        s_g[e][g] = pk(fmaf(am, y0, bm), fmaf(am, y1, bm));

        __syncthreads();

        if (type == 0) {
            u64 ig = s_g[e][unit];
            u64 fg = s_g[e][unit + 20];
            u64 gg = s_g[e][unit + 40];
            u64 og = s_g[e][unit + 60];
            c2 = ffma2(fg, c2, fmul2(ig, gg));
            float2 cf = upk(c2);
            float t0 = fmaf(2.f, sig1(2.f * cf.x), -1.f);
            float t1 = fmaf(2.f, sig1(2.f * cf.y), -1.f);
            u64 h2 = fmul2(og, pk(t0, t1));
            ((u64*)fn)[IN + unit] = h2;
            outp[(size_t)t * H_ + unit] = h2;
        }

        __syncthreads();
        cur ^= 1;
    }
}

// ============================================================================
// Layers 1/2: DPT kernel. 160 threads = 2 slots x 80; each slot runs 2 pairs.
// Roles: types 0,1 stage x for pair 0/1; types 2,3 own cell update pair 0/1.
// Every computed pointer/index is in-bounds regardless of guards.
// DST: 1 = g_buf0 -> g_buf1 ; 2 = g_buf1 -> FC head -> out
// ============================================================================
template <int DST>
__global__ __launch_bounds__(160, 3)
void lstm_l12(
    const float* __restrict__ W_ih,   // [80, 20]
    const float* __restrict__ W_hh,   // [80, 20]
    const float* __restrict__ b_ih,
    const float* __restrict__ b_hh,
    const float* __restrict__ fc1_w,
    const float* __restrict__ fc1_b,
    const float* __restrict__ fc2_w,
    const float* __restrict__ fc2_b,
    float* __restrict__ out_final)
{
    constexpr bool FINAL = (DST == 2);
    constexpr int IN = H_;               // 20
    constexpr int K2 = (IN + H_) / 2;    // 20 ulonglong2 per pair section

    __shared__ ulonglong2 s_hx[2][2][2][K2];   // [buf][slot][pair][q]
    __shared__ u64 s_g[2][2][G_];              // [slot][pair][gate]

    const int tid  = threadIdx.x;
    const int e    = tid / G_;           // slot 0..1
    const int g    = tid % G_;           // gate row 0..79
    const int unit = g % H_;             // 0..19
    const int type = g / H_;             // 0..3
    const size_t slot  = (size_t)blockIdx.x * 2 + e;
    const size_t pairA = 2 * slot;       // pairB = pairA + 1  (max 4095)

    // weights dup-packed (reused for both pairs): 40 u64
    u64 w2[2 * H_];
    #pragma unroll
    for (int k = 0; k < IN; ++k) { float w = __ldg(&W_ih[g * H_ + k]); w2[k] = pk(w, w); }
    #pragma unroll
    for (int k = 0; k < H_; ++k) { float w = __ldg(&W_hh[g * H_ + k]); w2[IN + k] = pk(w, w); }
    const float bb = __ldg(&b_ih[g]) + __ldg(&b_hh[g]);
    const u64 bias2 = pk(bb, bb);
    const float sc = (type == 2) ? -2.f : -1.f;
    const float am = (type == 2) ?  2.f :  1.f;
    const float bm = (type == 2) ? -1.f :  0.f;

    const u64* __restrict__ srcBase = (DST == 1) ? g_buf0 : g_buf1;
    const u64* __restrict__ srcA = srcBase + pairA * T_ * H_;
    const u64* __restrict__ srcB = srcA + (size_t)T_ * H_;
    u64* __restrict__ dstA = g_buf1 + pairA * T_ * H_;
    u64* __restrict__ dstB = dstA + (size_t)T_ * H_;

    // staging role (types 0,1): stage u64 slot `unit` of pair `type`
    const u64* __restrict__ mysrc = (type == 1) ? srcB : srcA;   // always valid
    const bool stg = (g < 2 * H_);                                // types 0,1
    // owner role (types 2,3): pair pp = type - 2
    u64* __restrict__ myout = (type == 3) ? dstB : dstA;          // always valid
    const bool own = (g >= 2 * H_);                               // types 2,3
    const int pp = own ? (type - 2) : 0;

    // prologue: stage x0, prefetch x1 (types 0,1); zero h slots (types 2,3)
    u64 xr = 0ULL;
    if (stg) {
        ((u64*)&s_hx[0][e][type][0])[unit] = mysrc[unit];
        xr = mysrc[H_ + unit];
    } else {
        ((u64*)&s_hx[0][e][pp][0])[IN + unit] = 0ULL;
    }
    __syncthreads();

    u64 c2 = 0ULL;
    int cur = 0;

    for (int t = 0; t < T_; ++t) {
        // stage x[t+1] into next buffer; prefetch x[t+2]
        if (stg) {
            if (t + 1 < T_) ((u64*)&s_hx[cur ^ 1][e][type][0])[unit] = xr;
            if (t + 2 < T_) xr = mysrc[(size_t)(t + 2) * H_ + unit];
        }

        // both pairs' gate dots: independent chains (ILP), uniform-address LDS
        const ulonglong2* hxA = &s_hx[cur][e][0][0];
        const ulonglong2* hxB = &s_hx[cur][e][1][0];
        u64 aA0 = bias2, aA1 = 0ULL, aB0 = bias2, aB1 = 0ULL;
        #pragma unroll
        for (int q = 0; q < K2; ++q) {
            ulonglong2 vA = hxA[q];
            ulonglong2 vB = hxB[q];
            aA0 = ffma2(vA.x, w2[2 * q],     aA0);
            aA1 = ffma2(vA.y, w2[2 * q + 1], aA1);
            aB0 = ffma2(vB.x, w2[2 * q],     aB0);
            aB1 = ffma2(vB.y, w2[2 * q + 1], aB1);
        }
        float2 aA = upk(fadd2(aA0, aA1));
        float2 aB = upk(fadd2(aB0, aB1));

        float yA0 = __fdividef(1.f, 1.f + __expf(sc * aA.x));
        float yA1 = __fdividef(1.f, 1.f + __expf(sc * aA.y));
        float yB0 = __fdividef(1.f, 1.f + __expf(sc * aB.x));
        float yB1 = __fdividef(1.f, 1.f + __expf(sc * aB.y));
        s_g[e][0][g] = pk(fmaf(am, yA0, bm), fmaf(am, yA1, bm));
        s_g[e][1][g] = pk(fmaf(am, yB0, bm), fmaf(am, yB1, bm));

        __syncthreads();

        if (own) {
            u64 ig = s_g[e][pp][unit];
            u64 fg = s_g[e][pp][unit + 20];
            u64 gg = s_g[e][pp][unit + 40];
            u64 og = s_g[e][pp][unit + 60];
            c2 = ffma2(fg, c2, fmul2(ig, gg));
            float2 cf = upk(c2);
            float t0 = fmaf(2.f, sig1(2.f * cf.x), -1.f);
            float t1 = fmaf(2.f, sig1(2.f * cf.y), -1.f);
            u64 h2 = fmul2(og, pk(t0, t1));
            ((u64*)&s_hx[cur ^ 1][e][pp][0])[IN + unit] = h2;
            if (!FINAL) myout[(size_t)t * H_ + unit] = h2;
        }

        __syncthreads();
        cur ^= 1;
    }

    if (FINAL) {
        if (own) {
            const u64* hfin = (const u64*)&s_hx[cur][e][pp][0] + IN;
            float b1 = __ldg(&fc1_b[unit]);
            u64 d2 = pk(b1, b1);
            #pragma unroll
            for (int k = 0; k < H_; ++k) {
                float w = __ldg(&fc1_w[unit * H_ + k]);
                d2 = ffma2(hfin[k], pk(w, w), d2);
            }
            float2 df = upk(d2);
            float wo = __ldg(&fc2_w[unit]);
            s_g[e][pp][unit] = pk(fmaxf(df.x, 0.f) * wo, fmaxf(df.y, 0.f) * wo);
        }
        __syncthreads();
        if (g == 40 || g == 60) {            // type2 unit0 -> pp0, type3 unit0 -> pp1
            const int po = (g - 40) / 20;
            float p0 = __ldg(&fc2_b[0]), p1 = p0;
            #pragma unroll
            for (int k = 0; k < H_; ++k) {
                float2 v = upk(s_g[e][po][k]);
                p0 += v.x; p1 += v.y;
            }
            *(float2*)&out_final[2 * (pairA + po)] = make_float2(p0, p1);
        }
    }
}

extern "C" void kernel_launch(void* const* d_in, const int* in_sizes, int n_in,
                              void* d_out, int out_size) {
    const float* x     = (const float*)d_in[0];
    const float* Wih0  = (const float*)d_in[1];
    const float* Whh0  = (const float*)d_in[2];
    const float* bih0  = (const float*)d_in[3];
    const float* bhh0  = (const float*)d_in[4];
    const float* Wih1  = (const float*)d_in[5];
    const float* Whh1  = (const float*)d_in[6];
    const float* bih1  = (const float*)d_in[7];
    const float* bhh1  = (const float*)d_in[8];
    const float* Wih2  = (const float*)d_in[9];
    const float* Whh2  = (const float*)d_in[10];
    const float* bih2  = (const float*)d_in[11];
    const float* bhh2  = (const float*)d_in[12];
    const float* fc1w  = (const float*)d_in[13];
    const float* fc1b  = (const float*)d_in[14];
    const float* fc2w  = (const float*)d_in[15];
    const float* fc2b  = (const float*)d_in[16];
    float* out = (float*)d_out;

    // Layer 0 (R4-proven): x -> g_buf0
    lstm_l0<<<NPAIR / PPB0, PPB0 * G_>>>(x, Wih0, Whh0, bih0, bhh0);
    // Layer 1 (DPT): g_buf0 -> g_buf1.  1024 blocks x 160 threads (4 pairs/block)
    lstm_l12<1><<<NPAIR / 4, 160>>>(
        Wih1, Whh1, bih1, bhh1, nullptr, nullptr, nullptr, nullptr, nullptr);
    // Layer 2 (DPT) + FC head: g_buf1 -> out
    lstm_l12<2><<<NPAIR / 4, 160>>>(
        Wih2, Whh2, bih2, bhh2, fc1w, fc1b, fc2w, fc2b, out);
}

// round 8
// speedup vs baseline: 1.5343x; 1.0562x over previous
#include <cuda_runtime.h>

// Problem constants
#define B_  8192
#define T_  336
#define F_  8
#define H_  20
#define G_  80
#define NPAIR (B_ / 2)   // 4096

typedef unsigned long long u64;

// Inter-layer hidden sequences, pair-interleaved: g_buf[pair][t][unit] = {h_e0, h_e1}
__device__ u64 g_buf0[(size_t)NPAIR * T_ * H_];
__device__ u64 g_buf1[(size_t)NPAIR * T_ * H_];

// ---- packed f32x2 helpers (sm_103a) ----
__device__ __forceinline__ u64 pk(float lo, float hi) {
    u64 r; asm("mov.b64 %0, {%1, %2};" : "=l"(r) : "f"(lo), "f"(hi)); return r;
}
__device__ __forceinline__ float2 upk(u64 v) {
    float2 f; asm("mov.b64 {%0, %1}, %2;" : "=f"(f.x), "=f"(f.y) : "l"(v)); return f;
}
__device__ __forceinline__ u64 ffma2(u64 a, u64 b, u64 c) {
    u64 d; asm("fma.rn.f32x2 %0, %1, %2, %3;" : "=l"(d) : "l"(a), "l"(b), "l"(c)); return d;
}
__device__ __forceinline__ u64 fmul2(u64 a, u64 b) {
    u64 d; asm("mul.rn.f32x2 %0, %1, %2;" : "=l"(d) : "l"(a), "l"(b)); return d;
}
__device__ __forceinline__ u64 fadd2(u64 a, u64 b) {
    u64 d; asm("add.rn.f32x2 %0, %1, %2;" : "=l"(d) : "l"(a), "l"(b)); return d;
}
__device__ __forceinline__ float sig1(float x) {
    return __fdividef(1.f, 1.f + __expf(-x));
}

// ============================================================================
// Layer 0: EXACT R4/R7 kernel (proven). IN=8, 4 pairs/block, 320 threads.
// ============================================================================
#define PPB0 4
__global__ __launch_bounds__(PPB0 * G_)
void lstm_l0(
    const float* __restrict__ in_seq,
    const float* __restrict__ W_ih,   // [80, 8]
    const float* __restrict__ W_hh,   // [80, 20]
    const float* __restrict__ b_ih,
    const float* __restrict__ b_hh)
{
    constexpr int IN = F_;
    constexpr int KTOT = IN + H_;
    constexpr int K2   = KTOT / 2;

    __shared__ ulonglong2 s_hx[2][PPB0][K2];
    __shared__ u64 s_g[PPB0][G_];

    const int tid  = threadIdx.x;
    const int e    = tid / G_;
    const int g    = tid % G_;
    const int unit = g % H_;
    const int type = g / H_;
    const size_t pair = (size_t)blockIdx.x * PPB0 + e;

    u64 w2[KTOT];
    #pragma unroll
    for (int k = 0; k < IN; ++k) { float w = __ldg(&W_ih[g * IN + k]); w2[k] = pk(w, w); }
    #pragma unroll
    for (int k = 0; k < H_; ++k) { float w = __ldg(&W_hh[g * H_ + k]); w2[IN + k] = pk(w, w); }
    const float bb = __ldg(&b_ih[g]) + __ldg(&b_hh[g]);
    const u64 bias2 = pk(bb, bb);
    const float sc = (type == 2) ? -2.f : -1.f;
    const float am = (type == 2) ?  2.f :  1.f;
    const float bm = (type == 2) ? -1.f :  0.f;

    const float* __restrict__ inp_f0 = in_seq + (size_t)(2 * pair)     * T_ * IN;
    const float* __restrict__ inp_f1 = in_seq + (size_t)(2 * pair + 1) * T_ * IN;
    u64* __restrict__ outp = g_buf0 + pair * T_ * H_;

    float xr_f = 0.f;
    const int kx = g >> 1, elx = g & 1;

    {
        float* f0 = (float*)&s_hx[0][e][0];
        if (g < 2 * IN) {
            const float* ip = elx ? inp_f1 : inp_f0;
            f0[2 * kx + elx] = ip[kx];
            xr_f = ip[IN + kx];
        }
        if (g >= 20 && g < 20 + H_)
            ((u64*)f0)[IN + (g - 20)] = 0ULL;
    }
    __syncthreads();

    u64 c2 = 0ULL;
    int cur = 0;

    for (int t = 0; t < T_; ++t) {
        float* fn = (float*)&s_hx[cur ^ 1][e][0];
        if (g < 2 * IN) {
            if (t + 1 < T_) fn[2 * kx + elx] = xr_f;
            if (t + 2 < T_) {
                const float* ip = elx ? inp_f1 : inp_f0;
                xr_f = ip[(size_t)(t + 2) * IN + kx];
            }
        }

        const ulonglong2* hx = &s_hx[cur][e][0];
        u64 acc0 = bias2, acc1 = pk(0.f, 0.f);
        #pragma unroll
        for (int q = 0; q < K2; ++q) {
            ulonglong2 v = hx[q];
            acc0 = ffma2(v.x, w2[2 * q],     acc0);
            acc1 = ffma2(v.y, w2[2 * q + 1], acc1);
        }
        float2 a = upk(fadd2(acc0, acc1));

        float y0 = __fdividef(1.f, 1.f + __expf(sc * a.x));
        float y1 = __fdividef(1.f, 1.f + __expf(sc * a.y));
        s_g[e][g] = pk(fmaf(am, y0, bm), fmaf(am, y1, bm));

        __syncthreads();

        if (type == 0) {
            u64 ig = s_g[e][unit];
            u64 fg = s_g[e][unit + 20];
            u64 gg = s_g[e][unit + 40];
            u64 og = s_g[e][unit + 60];
            c2 = ffma2(fg, c2, fmul2(ig, gg));
            float2 cf = upk(c2);
            float t0 = fmaf(2.f, sig1(2.f * cf.x), -1.f);
            float t1 = fmaf(2.f, sig1(2.f * cf.y), -1.f);
            u64 h2 = fmul2(og, pk(t0, t1));
            ((u64*)fn)[IN + unit] = h2;
            outp[(size_t)t * H_ + unit] = h2;
        }

        __syncthreads();
        cur ^= 1;
    }
}

// ============================================================================
// Layers 1/2: 80-thread blocks (1 slot, 2 pairs). K-split pipeline:
// the W_ih·x[t+1] half-dot is computed in the owner bubble of step t and
// carried in registers, so only the W_hh·h half is on the recurrence path.
// Roles: type0 owns pair A cells, type1 pair B; type2 stages pair A x,
// type3 pair B x. DST: 1 = g_buf0 -> g_buf1 ; 2 = g_buf1 -> FC head -> out
// ============================================================================
template <int DST>
__global__ __launch_bounds__(80, 6)
void lstm_l12(
    const float* __restrict__ W_ih,   // [80, 20]
    const float* __restrict__ W_hh,   // [80, 20]
    const float* __restrict__ b_ih,
    const float* __restrict__ b_hh,
    const float* __restrict__ fc1_w,
    const float* __restrict__ fc1_b,
    const float* __restrict__ fc2_w,
    const float* __restrict__ fc2_b,
    float* __restrict__ out_final)
{
    constexpr bool FINAL = (DST == 2);
    constexpr int Q = H_ / 2;            // 10 ulonglong2 per 20-u64 vector

    __shared__ ulonglong2 s_h [2][2][Q];   // [buf][pair][q]  hidden vec
    __shared__ ulonglong2 s_xv[2][2][Q];   // [buf][pair][q]  input  vec
    __shared__ u64 s_gt[2][G_];            // [pair][gate]

    const int g    = threadIdx.x;        // 0..79
    const int unit = g % H_;
    const int type = g / H_;
    const size_t pA = (size_t)blockIdx.x * 2;   // pairs pA, pA+1

    // weights dup-packed: 20 + 20 u64
    u64 wih[H_], whh[H_];
    #pragma unroll
    for (int k = 0; k < H_; ++k) { float w = __ldg(&W_ih[g * H_ + k]); wih[k] = pk(w, w); }
    #pragma unroll
    for (int k = 0; k < H_; ++k) { float w = __ldg(&W_hh[g * H_ + k]); whh[k] = pk(w, w); }
    const float bb = __ldg(&b_ih[g]) + __ldg(&b_hh[g]);
    const u64 bias2 = pk(bb, bb);
    const float sc = (type == 2) ? -2.f : -1.f;
    const float am = (type == 2) ?  2.f :  1.f;
    const float bm = (type == 2) ? -1.f :  0.f;

    const u64* __restrict__ srcBase = (DST == 1) ? g_buf0 : g_buf1;
    const u64* __restrict__ srcA = srcBase + pA * T_ * H_;
    const u64* __restrict__ srcB = srcA + (size_t)T_ * H_;
    u64* __restrict__ dstA = g_buf1 + pA * T_ * H_;
    u64* __restrict__ dstB = dstA + (size_t)T_ * H_;

    const bool own = (type < 2);                       // type0->A, type1->B
    const int  op  = (type == 1) ? 1 : 0;
    u64* __restrict__ myout = (type == 1) ? dstB : dstA;
    const bool stg = (type >= 2);                      // type2->A, type3->B
    const int  sp  = (type == 3) ? 1 : 0;
    const u64* __restrict__ mysrc = (type == 3) ? srcB : srcA;

    // ---- prologue: x[0] into buf0, h=0, prefetch x[1] ----
    u64 xr = 0ULL;
    if (stg) {
        ((u64*)&s_xv[0][sp][0])[unit] = mysrc[unit];
        xr = mysrc[H_ + unit];
    }
    if (own) ((u64*)&s_h[0][op][0])[unit] = 0ULL;
    __syncthreads();

    // xpart for t=0 (bias included), two chains per pair
    u64 xpA0, xpA1, xpB0, xpB1;
    {
        xpA0 = bias2; xpA1 = 0ULL; xpB0 = bias2; xpB1 = 0ULL;
        #pragma unroll
        for (int q = 0; q < Q; ++q) {
            ulonglong2 vA = s_xv[0][0][q];
            ulonglong2 vB = s_xv[0][1][q];
            xpA0 = ffma2(vA.x, wih[2 * q],     xpA0);
            xpA1 = ffma2(vA.y, wih[2 * q + 1], xpA1);
            xpB0 = ffma2(vB.x, wih[2 * q],     xpB0);
            xpB1 = ffma2(vB.y, wih[2 * q + 1], xpB1);
        }
    }

    u64 c2 = 0ULL;
    int cur = 0;

    for (int t = 0; t < T_; ++t) {
        // stage x[t+1] into nxt buffer; prefetch x[min(t+2, T-1)]
        if (stg) {
            ((u64*)&s_xv[cur ^ 1][sp][0])[unit] = xr;
            const int tn = (t + 2 < T_) ? t + 2 : T_ - 1;
            xr = mysrc[(size_t)tn * H_ + unit];
        }

        // recurrence-critical half-dot: h[t-1] only
        u64 aA0 = xpA0, aA1 = xpA1, aB0 = xpB0, aB1 = xpB1;
        #pragma unroll
        for (int q = 0; q < Q; ++q) {
            ulonglong2 vA = s_h[cur][0][q];
            ulonglong2 vB = s_h[cur][1][q];
            aA0 = ffma2(vA.x, whh[2 * q],     aA0);
            aA1 = ffma2(vA.y, whh[2 * q + 1], aA1);
            aB0 = ffma2(vB.x, whh[2 * q],     aB0);
            aB1 = ffma2(vB.y, whh[2 * q + 1], aB1);
        }
        float2 aA = upk(fadd2(aA0, aA1));
        float2 aB = upk(fadd2(aB0, aB1));

        float yA0 = __fdividef(1.f, 1.f + __expf(sc * aA.x));
        float yA1 = __fdividef(1.f, 1.f + __expf(sc * aA.y));
        float yB0 = __fdividef(1.f, 1.f + __expf(sc * aB.x));
        float yB1 = __fdividef(1.f, 1.f + __expf(sc * aB.y));
        s_gt[0][g] = pk(fmaf(am, yA0, bm), fmaf(am, yA1, bm));
        s_gt[1][g] = pk(fmaf(am, yB0, bm), fmaf(am, yB1, bm));

        __syncthreads();

        // owner bubble: cell update (types 0,1)
        if (own) {
            u64 ig = s_gt[op][unit];
            u64 fg = s_gt[op][unit + 20];
            u64 gg = s_gt[op][unit + 40];
            u64 og = s_gt[op][unit + 60];
            c2 = ffma2(fg, c2, fmul2(ig, gg));
            float2 cf = upk(c2);
            float t0 = fmaf(2.f, sig1(2.f * cf.x), -1.f);
            float t1 = fmaf(2.f, sig1(2.f * cf.y), -1.f);
            u64 h2 = fmul2(og, pk(t0, t1));
            ((u64*)&s_h[cur ^ 1][op][0])[unit] = h2;
            if (!FINAL) myout[(size_t)t * H_ + unit] = h2;
        }

        // bubble fill: xpart for t+1 from s_xv[nxt] (synced at the bar above)
        {
            xpA0 = bias2; xpA1 = 0ULL; xpB0 = bias2; xpB1 = 0ULL;
            const ulonglong2* xA = &s_xv[cur ^ 1][0][0];
            const ulonglong2* xB = &s_xv[cur ^ 1][1][0];
            #pragma unroll
            for (int q = 0; q < Q; ++q) {
                ulonglong2 vA = xA[q];
                ulonglong2 vB = xB[q];
                xpA0 = ffma2(vA.x, wih[2 * q],     xpA0);
                xpA1 = ffma2(vA.y, wih[2 * q + 1], xpA1);
                xpB0 = ffma2(vB.x, wih[2 * q],     xpB0);
                xpB1 = ffma2(vB.y, wih[2 * q + 1], xpB1);
            }
        }

        __syncthreads();
        cur ^= 1;
    }

    if (FINAL) {
        if (own) {
            const u64* hfin = (const u64*)&s_h[cur][op][0];
            float b1 = __ldg(&fc1_b[unit]);
            u64 d2 = pk(b1, b1);
            #pragma unroll
            for (int k = 0; k < H_; ++k) {
                float w = __ldg(&fc1_w[unit * H_ + k]);
                d2 = ffma2(hfin[k], pk(w, w), d2);
            }
            float2 df = upk(d2);
            float wo = __ldg(&fc2_w[unit]);
            s_gt[op][unit] = pk(fmaxf(df.x, 0.f) * wo, fmaxf(df.y, 0.f) * wo);
        }
        __syncthreads();
        if (g == 0 || g == 20) {
            const int po = (g == 20) ? 1 : 0;
            float p0 = __ldg(&fc2_b[0]), p1 = p0;
            #pragma unroll
            for (int k = 0; k < H_; ++k) {
                float2 v = upk(s_gt[po][k]);
                p0 += v.x; p1 += v.y;
            }
            *(float2*)&out_final[2 * (pA + po)] = make_float2(p0, p1);
        }
    }
}

extern "C" void kernel_launch(void* const* d_in, const int* in_sizes, int n_in,
                              void* d_out, int out_size) {
    const float* x     = (const float*)d_in[0];
    const float* Wih0  = (const float*)d_in[1];
    const float* Whh0  = (const float*)d_in[2];
    const float* bih0  = (const float*)d_in[3];
    const float* bhh0  = (const float*)d_in[4];
    const float* Wih1  = (const float*)d_in[5];
    const float* Whh1  = (const float*)d_in[6];
    const float* bih1  = (const float*)d_in[7];
    const float* bhh1  = (const float*)d_in[8];
    const float* Wih2  = (const float*)d_in[9];
    const float* Whh2  = (const float*)d_in[10];
    const float* bih2  = (const float*)d_in[11];
    const float* bhh2  = (const float*)d_in[12];
    const float* fc1w  = (const float*)d_in[13];
    const float* fc1b  = (const float*)d_in[14];
    const float* fc2w  = (const float*)d_in[15];
    const float* fc2b  = (const float*)d_in[16];
    float* out = (float*)d_out;

    // Layer 0 (proven): x -> g_buf0
    lstm_l0<<<NPAIR / PPB0, PPB0 * G_>>>(x, Wih0, Whh0, bih0, bhh0);
    // Layer 1: g_buf0 -> g_buf1   (2048 blocks x 80 threads, 2 pairs each)
    lstm_l12<1><<<NPAIR / 2, 80>>>(
        Wih1, Whh1, bih1, bhh1, nullptr, nullptr, nullptr, nullptr, nullptr);
    // Layer 2 + FC head: g_buf1 -> out
    lstm_l12<2><<<NPAIR / 2, 80>>>(
        Wih2, Whh2, bih2, bhh2, fc1w, fc1b, fc2w, fc2b, out);
}